// round 8
// baseline (speedup 1.0000x reference)
#include <cuda_runtime.h>
#include <cuda_bf16.h>
#include <math.h>
#include <stdint.h>

#define NB   8
#define CIN  64
#define CO   128
#define HH0  256
#define WW0  256
#define HWSZ 65536
#define HD   128
#define WD   128

// ---------------- scratch ----------------
__device__ float g_wsn[CO*CIN*9];
__device__ unsigned char g_wB[9*34816];     // per-tap [hi|lo][64 c-rows x 272B]
__device__ unsigned char g_gB[69632];       // gamma [hi|lo][128 o-rows x 272B]
__device__ float g_ratio[NB*HWSZ];
__device__ float g_mvalid[NB*HWSZ];
__device__ float g_y[(size_t)NB*CO*HWSZ];
__device__ float g_lor[(size_t)NB*CO*HD*WW0];
__device__ float g_hir[(size_t)NB*CO*HD*WW0];
__device__ float g_mlo[NB*HD*WW0];
__device__ float g_mhi[NB*HD*WW0];

__constant__ float c_H0[9] = {
    0.026748757410810f, -0.016864118442875f, -0.078223266528990f,
    0.266864118442875f,  0.602949018236360f,  0.266864118442875f,
   -0.078223266528990f, -0.016864118442875f,  0.026748757410810f};
__constant__ float c_H1[7] = {
    0.091271763114250f, -0.057543526228500f, -0.591271763114250f,
    1.115087052457000f, -0.591271763114250f, -0.057543526228500f,
    0.091271763114250f};

#define SZ_BAND ((size_t)NB*CO*HD*WD)
#define SZ_MASK ((size_t)NB*HD*WD)
#define OFS_LL   ((size_t)0)
#define OFS_MLL  (OFS_LL  + SZ_BAND)
#define OFS_LH   (OFS_MLL + SZ_MASK)
#define OFS_HL   (OFS_LH  + SZ_BAND)
#define OFS_HH   (OFS_HL  + SZ_BAND)
#define OFS_MLH  (OFS_HH  + SZ_BAND)
#define OFS_MHL  (OFS_MLH + SZ_MASK)
#define OFS_MHH  (OFS_MHL + SZ_MASK)

__device__ __forceinline__ int refl(int j, int n) {
    if (j < 0) j = -j;
    if (j >= n) j = 2*n - 2 - j;
    return j;
}

// ---------------- mma.sync / ldmatrix / cp.async helpers (baseline PTX, sm_80+) ----------
__device__ __forceinline__ uint32_t smem_u32(const void* p) {
    uint32_t a;
    asm("{ .reg .u64 t; cvta.to.shared.u64 t, %1; cvt.u32.u64 %0, t; }" : "=r"(a) : "l"(p));
    return a;
}
__device__ __forceinline__ void ldsm4(uint32_t* r, uint32_t a) {
    asm volatile("ldmatrix.sync.aligned.m8n8.x4.shared.b16 {%0,%1,%2,%3}, [%4];"
        : "=r"(r[0]), "=r"(r[1]), "=r"(r[2]), "=r"(r[3]) : "r"(a));
}
__device__ __forceinline__ void ldsm4t(uint32_t* r, uint32_t a) {
    asm volatile("ldmatrix.sync.aligned.m8n8.x4.trans.shared.b16 {%0,%1,%2,%3}, [%4];"
        : "=r"(r[0]), "=r"(r[1]), "=r"(r[2]), "=r"(r[3]) : "r"(a));
}
__device__ __forceinline__ void mma16816(float* c, const uint32_t* a, const uint32_t* b) {
    asm volatile("mma.sync.aligned.m16n8k16.row.col.f32.bf16.bf16.f32 "
        "{%0,%1,%2,%3},{%4,%5,%6,%7},{%8,%9},{%0,%1,%2,%3};"
        : "+f"(c[0]), "+f"(c[1]), "+f"(c[2]), "+f"(c[3])
        : "r"(a[0]), "r"(a[1]), "r"(a[2]), "r"(a[3]), "r"(b[0]), "r"(b[1]));
}
__device__ __forceinline__ void cpa16(uint32_t s, const void* g) {
    asm volatile("cp.async.cg.shared.global [%0], [%1], 16;" :: "r"(s), "l"(g) : "memory");
}
__device__ __forceinline__ void cpa_commit() {
    asm volatile("cp.async.commit_group;" ::: "memory");
}
__device__ __forceinline__ void cpa_wait1() {
    asm volatile("cp.async.wait_group 1;" ::: "memory");
}
__device__ __forceinline__ void cpa_wait0() {
    asm volatile("cp.async.wait_group 0;" ::: "memory");
}

// ---------------- K0: spectral norm -> g_wsn ----------------
__global__ void k_sigma(const float* __restrict__ w, const float* __restrict__ u) {
    __shared__ float sv[576];
    __shared__ float red[576];
    __shared__ float s_bcast;
    int t = threadIdx.x;

    float vj = 0.f;
    for (int o = 0; o < CO; ++o) vj += w[o*576 + t] * u[o];
    red[t] = vj*vj;
    sv[t] = vj;
    __syncthreads();
    if (t == 0) {
        float s = 0.f;
        for (int i = 0; i < 576; ++i) s += red[i];
        s_bcast = 1.f / (sqrtf(s) + 1e-12f);
    }
    __syncthreads();
    float vn = sv[t] * s_bcast;
    __syncthreads();
    sv[t] = vn;
    __syncthreads();

    if (t < CO) {
        float s = 0.f;
        for (int j = 0; j < 576; ++j) s += w[t*576 + j] * sv[j];
        red[t] = s*s;
    }
    __syncthreads();
    if (t == 0) {
        float s = 0.f;
        for (int i = 0; i < CO; ++i) s += red[i];
        s_bcast = 1.f / sqrtf(s);
    }
    __syncthreads();
    float inv_sigma = s_bcast;
    for (int i = t; i < CO*CIN*9; i += 576) g_wsn[i] = w[i] * inv_sigma;
}

// ---------------- K0b: weights -> per-tap [c][o] bf16 hi/lo rows (272B stride) --------
__global__ void k_prepw() {
    int idx = blockIdx.x*256 + threadIdx.x;
    if (idx >= 9*CIN*CO) return;
    int q = idx >> 13;
    int rem = idx & 8191;
    int c = rem >> 7;
    int o = rem & 127;
    float v = g_wsn[(o*CIN + c)*9 + q];
    __nv_bfloat16 hi = __float2bfloat16(v);
    __nv_bfloat16 lo = __float2bfloat16(v - __bfloat162float(hi));
    size_t base = (size_t)q*34816;
    *(__nv_bfloat16*)(g_wB + base +         c*272 + o*2) = hi;
    *(__nv_bfloat16*)(g_wB + base + 17408 + c*272 + o*2) = lo;
}

// ---------------- K0c: gamma -> [o][c] bf16 hi/lo rows (272B stride) ----------------
__global__ void k_prepg(const float* __restrict__ gamma) {
    int idx = blockIdx.x*256 + threadIdx.x;
    if (idx >= CO*CO) return;
    int o = idx >> 7;
    int c = idx & 127;
    float v = gamma[o*CO + c];
    __nv_bfloat16 hi = __float2bfloat16(v);
    __nv_bfloat16 lo = __float2bfloat16(v - __bfloat162float(hi));
    *(__nv_bfloat16*)(g_gB +         o*272 + c*2) = hi;
    *(__nv_bfloat16*)(g_gB + 34816 + o*272 + c*2) = lo;
}

// ---------------- K1: mask 3x3 box -> ratio + valid ----------------
__global__ void k_ratio(const float* __restrict__ mask) {
    int idx = blockIdx.x*256 + threadIdx.x;
    int b = idx >> 16;
    int hw = idx & 65535;
    int h = hw >> 8, wx = hw & 255;
    const float* mb = mask + (size_t)b*HWSZ;
    float s = 0.f;
    #pragma unroll
    for (int dh = -1; dh <= 1; ++dh) {
        int h2 = h + dh;
        if (h2 < 0 || h2 >= HH0) continue;
        #pragma unroll
        for (int dw = -1; dw <= 1; ++dw) {
            int w2 = wx + dw;
            if (w2 < 0 || w2 >= WW0) continue;
            s += mb[h2*WW0 + w2];
        }
    }
    bool valid = s > 0.f;
    g_mvalid[idx] = valid ? 1.f : 0.f;
    g_ratio[idx]  = valid ? 9.f / fmaxf(s, 1e-8f) : 0.f;
}

// ---------------- K2: fused conv + GDN via mma.sync (bf16 3-term splits) --------------
// Mainloop: conv implicit-GEMM (M=128px, N=128o, K=9x64).
// Epilogue: y = renorm+bias; z=y^2 -> smem bf16; s = gamma@z via mma; y*rsqrt(beta+s)*m -> g_y.
#define P_HI   0
#define P_LO   38016
#define BW0    76032
#define BW1    110848
#define GM_HI  145664           // gamma hi (34816) + lo (34816), cp.async at start
#define RT_SM  215296
#define BIAS_SM 215808
#define BETA_SM 216320
#define SMEM_MMA 216832
// epilogue-phase overlays (post-mainloop):
#define D_OFS  0                // D[o:128][px:130] f32 = 66560
#define Z_HI   66560            // z hi [c:128][272B]
#define Z_LO   101376           // z lo
#define S_OFS  66560            // s[o:128][px:130] f32 (overwrites z after mma)

extern __shared__ char smc[];

__global__ void __launch_bounds__(256) k_conv_mma(const float* __restrict__ x,
                                                  const float* __restrict__ mask,
                                                  const float* __restrict__ bias,
                                                  const float* __restrict__ beta) {
    uint32_t sb = smem_u32(smc);
    int t = threadIdx.x, l = t & 31, wid = t >> 5;
    int w0 = blockIdx.x * 64, h0 = blockIdx.y * 2, b = blockIdx.z;
    int warp_m = wid & 1;
    int warp_n = wid >> 1;

    // gamma prefetch FIRST (oldest group -> drained by the first wait_group 1)
    for (int i = t; i < 4352; i += 256)
        cpa16(sb + GM_HI + i*16, g_gB + i*16);
    cpa_commit();

    // ---- patch fill: 64c x 4rows x 66w of (x*mask), bf16 hi/lo ----
    for (int i = t; i < 16896; i += 256) {
        int w = i % 66;
        int rem = i / 66;
        int r = rem & 3;
        int c = rem >> 2;
        int h = h0 - 1 + r, wx = w0 - 1 + w;
        float v = 0.f;
        if (h >= 0 && h < HH0 && wx >= 0 && wx < WW0)
            v = x[(((size_t)b*CIN + c)*HH0 + h)*WW0 + wx]
              * mask[((size_t)b*HH0 + h)*WW0 + wx];
        __nv_bfloat16 hi = __float2bfloat16(v);
        __nv_bfloat16 lo = __float2bfloat16(v - __bfloat162float(hi));
        int off = (r*66 + w)*144 + c*2;
        *(__nv_bfloat16*)(smc + P_HI + off) = hi;
        *(__nv_bfloat16*)(smc + P_LO + off) = lo;
    }

    for (int i = t; i < 2176; i += 256)
        cpa16(sb + BW0 + i*16, g_wB + (size_t)0*34816 + i*16);
    cpa_commit();
    for (int i = t; i < 2176; i += 256)
        cpa16(sb + BW1 + i*16, g_wB + (size_t)1*34816 + i*16);
    cpa_commit();
    cpa_wait1();
    __syncthreads();

    float acc[4][4][4];
    #pragma unroll
    for (int mi = 0; mi < 4; ++mi)
        #pragma unroll
        for (int ni = 0; ni < 4; ++ni)
            #pragma unroll
            for (int k = 0; k < 4; ++k) acc[mi][ni][k] = 0.f;

    int lane15 = l & 15;
    int kh8 = ((l >> 4) & 1) * 8;
    int noff = ((l >> 4) & 1) * 8;

    for (int q = 0; q < 9; ++q) {
        int kh = q / 3, kw = q - kh*3;
        uint32_t bwbase = sb + ((q & 1) ? BW1 : BW0);
        int prow0 = ((warp_m + kh)*66 + kw) * 144;

        #pragma unroll
        for (int ks = 0; ks < 4; ++ks) {
            int k0 = ks * 16;
            uint32_t aH[4][4], aL[4][4];
            #pragma unroll
            for (int mi = 0; mi < 4; ++mi) {
                uint32_t off = (uint32_t)(prow0 + (mi*16 + lane15)*144 + (k0 + kh8)*2);
                ldsm4(aH[mi], sb + P_HI + off);
                ldsm4(aL[mi], sb + P_LO + off);
            }
            uint32_t bH[2][4], bL[2][4];
            #pragma unroll
            for (int n2 = 0; n2 < 2; ++n2) {
                uint32_t boff = (uint32_t)((k0 + lane15)*272 + (warp_n*32 + n2*16 + noff)*2);
                ldsm4t(bH[n2], bwbase + boff);
                ldsm4t(bL[n2], bwbase + 17408 + boff);
            }
            #pragma unroll
            for (int mi = 0; mi < 4; ++mi)
                #pragma unroll
                for (int ni = 0; ni < 4; ++ni) {
                    const uint32_t* bh = &bH[ni >> 1][(ni & 1)*2];
                    const uint32_t* bl = &bL[ni >> 1][(ni & 1)*2];
                    mma16816(acc[mi][ni], aH[mi], bh);
                    mma16816(acc[mi][ni], aH[mi], bl);
                    mma16816(acc[mi][ni], aL[mi], bh);
                }
        }

        __syncthreads();
        if (q < 8) {
            if (q < 7) {
                uint32_t dst = sb + ((q & 1) ? BW1 : BW0);
                const unsigned char* src = g_wB + (size_t)(q + 2)*34816;
                for (int i = t; i < 2176; i += 256)
                    cpa16(dst + i*16, src + i*16);
            }
            cpa_commit();
            cpa_wait1();
            __syncthreads();
        }
    }

    // ---- Phase A: conv frags -> D[o][px], px = warp_m*64 + ... (px<64: row h0; else h0+1)
    float* D = (float*)(smc + D_OFS);
    float* rt_sm = (float*)(smc + RT_SM);
    float* bias_sm = (float*)(smc + BIAS_SM);
    float* beta_sm = (float*)(smc + BETA_SM);
    #pragma unroll
    for (int mi = 0; mi < 4; ++mi)
        #pragma unroll
        for (int ni = 0; ni < 4; ++ni) {
            int px = warp_m*64 + mi*16 + (l >> 2);
            int o  = warp_n*32 + ni*8 + 2*(l & 3);
            D[o*130 + px]           = acc[mi][ni][0];
            D[(o + 1)*130 + px]     = acc[mi][ni][1];
            D[o*130 + px + 8]       = acc[mi][ni][2];
            D[(o + 1)*130 + px + 8] = acc[mi][ni][3];
        }
    if (t < 128) {
        rt_sm[t] = g_ratio[((size_t)b*HH0 + h0 + (t >> 6))*WW0 + w0 + (t & 63)];
        bias_sm[t] = bias[t];
        beta_sm[t] = beta[t];
    }
    __syncthreads();

    // ---- Phase B: z = (renorm(D)+bias)^2 -> bf16 hi/lo [c][px], 272B rows ----
    for (int i = t; i < 8192; i += 256) {
        int c = i >> 6, pp = (i & 63) * 2;
        float2 raw = *(float2*)&D[c*130 + pp];
        float r0 = rt_sm[pp], r1 = rt_sm[pp + 1];
        float bv = bias_sm[c];
        float y0 = (r0 > 0.f) ? raw.x*r0 + bv : 0.f;
        float y1 = (r1 > 0.f) ? raw.y*r1 + bv : 0.f;
        float z0 = y0*y0, z1 = y1*y1;
        __nv_bfloat162 hp, lp;
        hp.x = __float2bfloat16(z0);
        hp.y = __float2bfloat16(z1);
        lp.x = __float2bfloat16(z0 - __bfloat162float(hp.x));
        lp.y = __float2bfloat16(z1 - __bfloat162float(hp.y));
        int off = c*272 + pp*2;
        *(__nv_bfloat162*)(smc + Z_HI + off) = hp;
        *(__nv_bfloat162*)(smc + Z_LO + off) = lp;
    }
    cpa_wait0();         // gamma resident (long since)
    __syncthreads();

    // ---- Phase C: s = gamma @ z (3-term bf16 split), K = 128 c ----
    float sacc[4][4][4];
    #pragma unroll
    for (int mi = 0; mi < 4; ++mi)
        #pragma unroll
        for (int ni = 0; ni < 4; ++ni)
            #pragma unroll
            for (int k = 0; k < 4; ++k) sacc[mi][ni][k] = 0.f;

    #pragma unroll
    for (int ks = 0; ks < 8; ++ks) {
        int k0 = ks * 16;
        uint32_t aH[4][4], aL[4][4];
        #pragma unroll
        for (int mi = 0; mi < 4; ++mi) {
            uint32_t off = (uint32_t)((warp_m*64 + mi*16 + lane15)*272 + (k0 + kh8)*2);
            ldsm4(aH[mi], sb + GM_HI + off);
            ldsm4(aL[mi], sb + GM_HI + 34816 + off);
        }
        uint32_t bH[2][4], bL[2][4];
        #pragma unroll
        for (int n2 = 0; n2 < 2; ++n2) {
            uint32_t boff = (uint32_t)((k0 + lane15)*272 + (warp_n*32 + n2*16 + noff)*2);
            ldsm4t(bH[n2], sb + Z_HI + boff);
            ldsm4t(bL[n2], sb + Z_LO + boff);
        }
        #pragma unroll
        for (int mi = 0; mi < 4; ++mi)
            #pragma unroll
            for (int ni = 0; ni < 4; ++ni) {
                const uint32_t* bh = &bH[ni >> 1][(ni & 1)*2];
                const uint32_t* bl = &bL[ni >> 1][(ni & 1)*2];
                mma16816(sacc[mi][ni], aH[mi], bh);
                mma16816(sacc[mi][ni], aH[mi], bl);
                mma16816(sacc[mi][ni], aL[mi], bh);
            }
    }

    // ---- Phase D: s frags -> S[o][px] (overwrites z region) ----
    __syncthreads();
    float* S = (float*)(smc + S_OFS);
    #pragma unroll
    for (int mi = 0; mi < 4; ++mi)
        #pragma unroll
        for (int ni = 0; ni < 4; ++ni) {
            int o  = warp_m*64 + mi*16 + (l >> 2);
            int px = warp_n*32 + ni*8 + 2*(l & 3);
            S[o*130 + px]           = sacc[mi][ni][0];
            S[o*130 + px + 1]       = sacc[mi][ni][1];
            S[(o + 8)*130 + px]     = sacc[mi][ni][2];
            S[(o + 8)*130 + px + 1] = sacc[mi][ni][3];
        }
    __syncthreads();

    // ---- Phase E: final y*rsqrt(beta+s)*mask -> g_y, coalesced ----
    int wp = t & 63, og = t >> 6;
    #pragma unroll
    for (int r = 0; r < 2; ++r) {
        int h = h0 + r;
        int wg = w0 + wp;
        float rtv = rt_sm[r*64 + wp];
        #pragma unroll 8
        for (int oo = 0; oo < 32; ++oo) {
            int o = oo*4 + og;
            float raw = D[o*130 + r*64 + wp];
            float s = S[o*130 + r*64 + wp];
            float y = raw*rtv + bias_sm[o];
            float outv = (rtv > 0.f) ? y * rsqrtf(beta_sm[o] + s) : 0.f;
            g_y[(((size_t)b*CO + o)*HH0 + h)*WW0 + wg] = outv;
        }
    }
}

// ---------------- K4: DWT row filters ----------------
__global__ void k_dwt_rows() {
    size_t idx = (size_t)blockIdx.x*256 + threadIdx.x;
    int wx = (int)(idx & 255);
    int hr = (int)((idx >> 8) & 127);
    int bc = (int)(idx >> 15);
    const float* col = g_y + (size_t)bc*HWSZ + wx;
    float r[9];
    #pragma unroll
    for (int k = 0; k < 9; ++k)
        r[k] = col[refl(2*hr + k - 4, HH0) * WW0];
    float lo = 0.f, hi = 0.f;
    #pragma unroll
    for (int k = 0; k < 9; ++k) lo += c_H0[k]*r[k];
    #pragma unroll
    for (int k = 0; k < 7; ++k) hi += c_H1[k]*r[k+1];
    g_lor[idx] = lo;
    g_hir[idx] = hi;
}

// ---------------- K5: DWT col filters -> 4 bands ----------------
__global__ void k_dwt_cols(float* __restrict__ out) {
    size_t idx = (size_t)blockIdx.x*256 + threadIdx.x;
    int wr = (int)(idx & 127);
    int hr = (int)((idx >> 7) & 127);
    int bc = (int)(idx >> 14);
    const float* lrow = g_lor + ((size_t)bc*HD + hr)*WW0;
    const float* hrow = g_hir + ((size_t)bc*HD + hr)*WW0;
    float rl[9], rh[9];
    #pragma unroll
    for (int k = 0; k < 9; ++k) {
        int j = refl(2*wr + k - 4, WW0);
        rl[k] = lrow[j];
        rh[k] = hrow[j];
    }
    float ll = 0.f, lh = 0.f, hl = 0.f, hh = 0.f;
    #pragma unroll
    for (int k = 0; k < 9; ++k) { ll += c_H0[k]*rl[k]; hl += c_H0[k]*rh[k]; }
    #pragma unroll
    for (int k = 0; k < 7; ++k) { lh += c_H1[k]*rl[k+1]; hh += c_H1[k]*rh[k+1]; }
    out[OFS_LL + idx] = ll;
    out[OFS_LH + idx] = lh;
    out[OFS_HL + idx] = hl;
    out[OFS_HH + idx] = hh;
}

// ---------------- K6: mask downsample along H ----------------
__global__ void k_mask_rows() {
    int idx = blockIdx.x*256 + threadIdx.x;
    int wx = idx & 255;
    int hr = (idx >> 8) & 127;
    int b  = idx >> 15;
    const float* mb = g_mvalid + (size_t)b*HWSZ + wx;
    float s9 = 0.f, s7 = 0.f;
    #pragma unroll
    for (int k = 0; k < 9; ++k) {
        float v = mb[refl(2*hr + k - 4, HH0) * WW0];
        s9 += v;
        if (k >= 1 && k <= 7) s7 += v;
    }
    g_mlo[idx] = (s9 > 0.f) ? 1.f : 0.f;
    g_mhi[idx] = (s7 > 0.f) ? 1.f : 0.f;
}

// ---------------- K7: mask downsample along W -> out ----------------
__global__ void k_mask_cols(float* __restrict__ out) {
    int idx = blockIdx.x*256 + threadIdx.x;
    int wr = idx & 127;
    int hr = (idx >> 7) & 127;
    int b  = idx >> 14;
    const float* lrow = g_mlo + ((size_t)b*HD + hr)*WW0;
    const float* hrow = g_mhi + ((size_t)b*HD + hr)*WW0;
    float s9l = 0.f, s7l = 0.f, s9h = 0.f, s7h = 0.f;
    #pragma unroll
    for (int k = 0; k < 9; ++k) {
        int j = refl(2*wr + k - 4, WW0);
        float vl = lrow[j], vh = hrow[j];
        s9l += vl; s9h += vh;
        if (k >= 1 && k <= 7) { s7l += vl; s7h += vh; }
    }
    out[OFS_MLL + idx] = (s9l > 0.f) ? 1.f : 0.f;
    out[OFS_MLH + idx] = (s7l > 0.f) ? 1.f : 0.f;
    out[OFS_MHL + idx] = (s9h > 0.f) ? 1.f : 0.f;
    out[OFS_MHH + idx] = (s7h > 0.f) ? 1.f : 0.f;
}

// ---------------- launch ----------------
extern "C" void kernel_launch(void* const* d_in, const int* in_sizes, int n_in,
                              void* d_out, int out_size) {
    const float* tensor = (const float*)d_in[0];
    const float* mask   = (const float*)d_in[1];
    const float* weight = (const float*)d_in[2];
    const float* bias   = (const float*)d_in[3];
    const float* u      = (const float*)d_in[4];
    const float* beta   = (const float*)d_in[5];
    const float* gamma  = (const float*)d_in[6];
    float* out = (float*)d_out;

    cudaFuncSetAttribute(k_conv_mma, cudaFuncAttributeMaxDynamicSharedMemorySize, SMEM_MMA);

    k_sigma<<<1, 576>>>(weight, u);
    k_prepw<<<288, 256>>>();
    k_prepg<<<64, 256>>>(gamma);
    k_ratio<<<(NB*HWSZ)/256, 256>>>(mask);
    k_conv_mma<<<dim3(4, 128, NB), 256, SMEM_MMA>>>(tensor, mask, bias, beta);
    k_dwt_rows<<<(int)(((size_t)NB*CO*HD*WW0)/256), 256>>>();
    k_dwt_cols<<<(int)(((size_t)NB*CO*HD*WD)/256), 256>>>(out);
    k_mask_rows<<<(NB*HD*WW0)/256, 256>>>();
    k_mask_cols<<<(NB*HD*WD)/256, 256>>>(out);
}

// round 9
// speedup vs baseline: 1.1971x; 1.1971x over previous
#include <cuda_runtime.h>
#include <cuda_bf16.h>
#include <math.h>
#include <stdint.h>

#define NB   8
#define CIN  64
#define CO   128
#define HH0  256
#define WW0  256
#define HWSZ 65536
#define HD   128
#define WD   128

// ---------------- scratch ----------------
__device__ float g_wsn[CO*CIN*9];
__device__ unsigned char g_wB[9*34816];     // per-tap [hi|lo][64 c-rows x 272B (128 o bf16 + pad)]
__device__ float g_ratio[NB*HWSZ];
__device__ float g_mvalid[NB*HWSZ];
__device__ float g_y[(size_t)NB*CO*HWSZ];
__device__ float g_mlo[NB*HD*WW0];
__device__ float g_mhi[NB*HD*WW0];

__constant__ float c_H0[9] = {
    0.026748757410810f, -0.016864118442875f, -0.078223266528990f,
    0.266864118442875f,  0.602949018236360f,  0.266864118442875f,
   -0.078223266528990f, -0.016864118442875f,  0.026748757410810f};
__constant__ float c_H1[7] = {
    0.091271763114250f, -0.057543526228500f, -0.591271763114250f,
    1.115087052457000f, -0.591271763114250f, -0.057543526228500f,
    0.091271763114250f};

#define SZ_BAND ((size_t)NB*CO*HD*WD)
#define SZ_MASK ((size_t)NB*HD*WD)
#define OFS_LL   ((size_t)0)
#define OFS_MLL  (OFS_LL  + SZ_BAND)
#define OFS_LH   (OFS_MLL + SZ_MASK)
#define OFS_HL   (OFS_LH  + SZ_BAND)
#define OFS_HH   (OFS_HL  + SZ_BAND)
#define OFS_MLH  (OFS_HH  + SZ_BAND)
#define OFS_MHL  (OFS_MLH + SZ_MASK)
#define OFS_MHH  (OFS_MHL + SZ_MASK)

__device__ __forceinline__ int refl(int j, int n) {
    if (j < 0) j = -j;
    if (j >= n) j = 2*n - 2 - j;
    return j;
}

// ---------------- mma.sync / ldmatrix / cp.async helpers (baseline PTX, sm_80+) ----------
__device__ __forceinline__ uint32_t smem_u32(const void* p) {
    uint32_t a;
    asm("{ .reg .u64 t; cvta.to.shared.u64 t, %1; cvt.u32.u64 %0, t; }" : "=r"(a) : "l"(p));
    return a;
}
__device__ __forceinline__ void ldsm4(uint32_t* r, uint32_t a) {
    asm volatile("ldmatrix.sync.aligned.m8n8.x4.shared.b16 {%0,%1,%2,%3}, [%4];"
        : "=r"(r[0]), "=r"(r[1]), "=r"(r[2]), "=r"(r[3]) : "r"(a));
}
__device__ __forceinline__ void ldsm4t(uint32_t* r, uint32_t a) {
    asm volatile("ldmatrix.sync.aligned.m8n8.x4.trans.shared.b16 {%0,%1,%2,%3}, [%4];"
        : "=r"(r[0]), "=r"(r[1]), "=r"(r[2]), "=r"(r[3]) : "r"(a));
}
__device__ __forceinline__ void mma16816(float* c, const uint32_t* a, const uint32_t* b) {
    asm volatile("mma.sync.aligned.m16n8k16.row.col.f32.bf16.bf16.f32 "
        "{%0,%1,%2,%3},{%4,%5,%6,%7},{%8,%9},{%0,%1,%2,%3};"
        : "+f"(c[0]), "+f"(c[1]), "+f"(c[2]), "+f"(c[3])
        : "r"(a[0]), "r"(a[1]), "r"(a[2]), "r"(a[3]), "r"(b[0]), "r"(b[1]));
}
__device__ __forceinline__ void cpa16(uint32_t s, const void* g) {
    asm volatile("cp.async.cg.shared.global [%0], [%1], 16;" :: "r"(s), "l"(g) : "memory");
}
__device__ __forceinline__ void cpa_commit() {
    asm volatile("cp.async.commit_group;" ::: "memory");
}
__device__ __forceinline__ void cpa_wait1() {
    asm volatile("cp.async.wait_group 1;" ::: "memory");
}

// ---------------- K0: spectral norm -> g_wsn ----------------
__global__ void k_sigma(const float* __restrict__ w, const float* __restrict__ u) {
    __shared__ float sv[576];
    __shared__ float red[576];
    __shared__ float s_bcast;
    int t = threadIdx.x;

    float vj = 0.f;
    for (int o = 0; o < CO; ++o) vj += w[o*576 + t] * u[o];
    red[t] = vj*vj;
    sv[t] = vj;
    __syncthreads();
    if (t == 0) {
        float s = 0.f;
        for (int i = 0; i < 576; ++i) s += red[i];
        s_bcast = 1.f / (sqrtf(s) + 1e-12f);
    }
    __syncthreads();
    float vn = sv[t] * s_bcast;
    __syncthreads();
    sv[t] = vn;
    __syncthreads();

    if (t < CO) {
        float s = 0.f;
        for (int j = 0; j < 576; ++j) s += w[t*576 + j] * sv[j];
        red[t] = s*s;
    }
    __syncthreads();
    if (t == 0) {
        float s = 0.f;
        for (int i = 0; i < CO; ++i) s += red[i];
        s_bcast = 1.f / sqrtf(s);
    }
    __syncthreads();
    float inv_sigma = s_bcast;
    for (int i = t; i < CO*CIN*9; i += 576) g_wsn[i] = w[i] * inv_sigma;
}

// ---------------- K0b: weights -> per-tap [c][o] bf16 hi/lo rows (272B stride) --------
__global__ void k_prepw() {
    int idx = blockIdx.x*256 + threadIdx.x;
    if (idx >= 9*CIN*CO) return;
    int q = idx >> 13;
    int rem = idx & 8191;
    int c = rem >> 7;
    int o = rem & 127;
    float v = g_wsn[(o*CIN + c)*9 + q];
    __nv_bfloat16 hi = __float2bfloat16(v);
    __nv_bfloat16 lo = __float2bfloat16(v - __bfloat162float(hi));
    size_t base = (size_t)q*34816;
    *(__nv_bfloat16*)(g_wB + base +         c*272 + o*2) = hi;
    *(__nv_bfloat16*)(g_wB + base + 17408 + c*272 + o*2) = lo;
}

// ---------------- K1: mask 3x3 box -> ratio + valid ----------------
__global__ void k_ratio(const float* __restrict__ mask) {
    int idx = blockIdx.x*256 + threadIdx.x;
    int b = idx >> 16;
    int hw = idx & 65535;
    int h = hw >> 8, wx = hw & 255;
    const float* mb = mask + (size_t)b*HWSZ;
    float s = 0.f;
    #pragma unroll
    for (int dh = -1; dh <= 1; ++dh) {
        int h2 = h + dh;
        if (h2 < 0 || h2 >= HH0) continue;
        #pragma unroll
        for (int dw = -1; dw <= 1; ++dw) {
            int w2 = wx + dw;
            if (w2 < 0 || w2 >= WW0) continue;
            s += mb[h2*WW0 + w2];
        }
    }
    bool valid = s > 0.f;
    g_mvalid[idx] = valid ? 1.f : 0.f;
    g_ratio[idx]  = valid ? 9.f / fmaxf(s, 1e-8f) : 0.f;
}

// ---------------- K2: mma.sync implicit-GEMM conv (bf16 3-term split) ----------------
#define P_HI 0
#define P_LO 38016
#define BW0  76032
#define BW1  110848
#define SMEM_MMA 145664

extern __shared__ char smc[];

__global__ void __launch_bounds__(256) k_conv_mma(const float* __restrict__ x,
                                                  const float* __restrict__ mask,
                                                  const float* __restrict__ bias) {
    uint32_t sb = smem_u32(smc);
    int t = threadIdx.x, l = t & 31, wid = t >> 5;
    int w0 = blockIdx.x * 64, h0 = blockIdx.y * 2, b = blockIdx.z;
    int warp_m = wid & 1;
    int warp_n = wid >> 1;

    for (int i = t; i < 16896; i += 256) {
        int w = i % 66;
        int rem = i / 66;
        int r = rem & 3;
        int c = rem >> 2;
        int h = h0 - 1 + r, wx = w0 - 1 + w;
        float v = 0.f;
        if (h >= 0 && h < HH0 && wx >= 0 && wx < WW0)
            v = x[(((size_t)b*CIN + c)*HH0 + h)*WW0 + wx]
              * mask[((size_t)b*HH0 + h)*WW0 + wx];
        __nv_bfloat16 hi = __float2bfloat16(v);
        __nv_bfloat16 lo = __float2bfloat16(v - __bfloat162float(hi));
        int off = (r*66 + w)*144 + c*2;
        *(__nv_bfloat16*)(smc + P_HI + off) = hi;
        *(__nv_bfloat16*)(smc + P_LO + off) = lo;
    }

    for (int i = t; i < 2176; i += 256)
        cpa16(sb + BW0 + i*16, g_wB + (size_t)0*34816 + i*16);
    cpa_commit();
    for (int i = t; i < 2176; i += 256)
        cpa16(sb + BW1 + i*16, g_wB + (size_t)1*34816 + i*16);
    cpa_commit();
    cpa_wait1();
    __syncthreads();

    float acc[4][4][4];
    #pragma unroll
    for (int mi = 0; mi < 4; ++mi)
        #pragma unroll
        for (int ni = 0; ni < 4; ++ni)
            #pragma unroll
            for (int k = 0; k < 4; ++k) acc[mi][ni][k] = 0.f;

    int lane15 = l & 15;
    int kh8 = ((l >> 4) & 1) * 8;
    int noff = ((l >> 4) & 1) * 8;

    for (int q = 0; q < 9; ++q) {
        int kh = q / 3, kw = q - kh*3;
        uint32_t bwbase = sb + ((q & 1) ? BW1 : BW0);
        int prow0 = ((warp_m + kh)*66 + kw) * 144;

        #pragma unroll
        for (int ks = 0; ks < 4; ++ks) {
            int k0 = ks * 16;
            uint32_t aH[4][4], aL[4][4];
            #pragma unroll
            for (int mi = 0; mi < 4; ++mi) {
                uint32_t off = (uint32_t)(prow0 + (mi*16 + lane15)*144 + (k0 + kh8)*2);
                ldsm4(aH[mi], sb + P_HI + off);
                ldsm4(aL[mi], sb + P_LO + off);
            }
            uint32_t bH[2][4], bL[2][4];
            #pragma unroll
            for (int n2 = 0; n2 < 2; ++n2) {
                uint32_t boff = (uint32_t)((k0 + lane15)*272 + (warp_n*32 + n2*16 + noff)*2);
                ldsm4t(bH[n2], bwbase + boff);
                ldsm4t(bL[n2], bwbase + 17408 + boff);
            }
            #pragma unroll
            for (int mi = 0; mi < 4; ++mi)
                #pragma unroll
                for (int ni = 0; ni < 4; ++ni) {
                    const uint32_t* bh = &bH[ni >> 1][(ni & 1)*2];
                    const uint32_t* bl = &bL[ni >> 1][(ni & 1)*2];
                    mma16816(acc[mi][ni], aH[mi], bh);
                    mma16816(acc[mi][ni], aH[mi], bl);
                    mma16816(acc[mi][ni], aL[mi], bh);
                }
        }

        __syncthreads();
        if (q < 8) {
            if (q < 7) {
                uint32_t dst = sb + ((q & 1) ? BW1 : BW0);
                const unsigned char* src = g_wB + (size_t)(q + 2)*34816;
                for (int i = t; i < 2176; i += 256)
                    cpa16(dst + i*16, src + i*16);
            }
            cpa_commit();
            cpa_wait1();
            __syncthreads();
        }
    }

    __syncthreads();
    float* D = (float*)smc;
    #pragma unroll
    for (int mi = 0; mi < 4; ++mi)
        #pragma unroll
        for (int ni = 0; ni < 4; ++ni) {
            int px = warp_m*64 + mi*16 + (l >> 2);
            int o  = warp_n*32 + ni*8 + 2*(l & 3);
            D[o*130 + px]           = acc[mi][ni][0];
            D[(o + 1)*130 + px]     = acc[mi][ni][1];
            D[o*130 + px + 8]       = acc[mi][ni][2];
            D[(o + 1)*130 + px + 8] = acc[mi][ni][3];
        }
    __syncthreads();

    int wp = t & 63, og = t >> 6;
    #pragma unroll
    for (int r = 0; r < 2; ++r) {
        int h = h0 + r;
        int wg = w0 + wp;
        float rt = g_ratio[((size_t)b*HH0 + h)*WW0 + wg];
        #pragma unroll 8
        for (int oo = 0; oo < 32; ++oo) {
            int o = oo*4 + og;
            float v = D[o*130 + r*64 + wp];
            g_y[(((size_t)b*CO + o)*HH0 + h)*WW0 + wg] = (rt > 0.f) ? v*rt + bias[o] : 0.f;
        }
    }
}

// ---------------- K3: GDN (in-place), scalar tiled GEMM (proven R1 version) ----------
__global__ void __launch_bounds__(256) k_gdn(const float* __restrict__ gamma,
                                             const float* __restrict__ beta) {
    __shared__ float zs[16][128];
    __shared__ float gs[128][17];

    size_t p0 = (size_t)blockIdx.x * 128;
    int b   = (int)(p0 >> 16);
    int hw0 = (int)(p0 & 65535);
    int t = threadIdx.x;
    int px = t & 15, oy = t >> 4;

    float acc[8][8];
    #pragma unroll
    for (int i = 0; i < 8; ++i)
        #pragma unroll
        for (int j = 0; j < 8; ++j) acc[i][j] = 0.f;

    float* yb = g_y + (size_t)b*CO*HWSZ + hw0;

    for (int c0 = 0; c0 < CO; c0 += 16) {
        __syncthreads();
        for (int i = t; i < 2048; i += 256) {
            int k = i >> 7, p = i & 127;
            float v = yb[(size_t)(c0 + k)*HWSZ + p];
            zs[k][p] = v*v;
        }
        for (int i = t; i < 2048; i += 256) {
            int o = i >> 4, k = i & 15;
            gs[o][k] = gamma[o*CO + c0 + k];
        }
        __syncthreads();
        #pragma unroll
        for (int k = 0; k < 16; ++k) {
            float a[8], bb[8];
            #pragma unroll
            for (int i = 0; i < 8; ++i) a[i] = gs[oy*8 + i][k];
            #pragma unroll
            for (int j = 0; j < 8; ++j) bb[j] = zs[k][px + 16*j];
            #pragma unroll
            for (int i = 0; i < 8; ++i)
                #pragma unroll
                for (int j = 0; j < 8; ++j) acc[i][j] += a[i]*bb[j];
        }
    }

    #pragma unroll
    for (int i = 0; i < 8; ++i) {
        int o = oy*8 + i;
        float bo = beta[o];
        #pragma unroll
        for (int j = 0; j < 8; ++j) {
            int p = px + 16*j;
            size_t ad = (size_t)o*HWSZ + p;
            float xv = yb[ad];
            float mv = g_mvalid[p0 + p];
            yb[ad] = xv * rsqrtf(bo + acc[i][j]) * mv;
        }
    }
}

// ---------------- K4: fused DWT (rows + cols in one pass) -> 4 bands ----------------
// CTA = one (b,c) image x 16 output rows. Stage 39x256 input rows (reflect),
// row-filter into lo/hi[16][260], col-filter (reflect) -> bands to d_out.
#define DX_OFS 0          // xs[39][256] floats
#define DL_OFS 9984       // lo[16][260]
#define DH_OFS 14144      // hi[16][260]
#define SMEM_DWT 73216    // 18304 floats

__global__ void __launch_bounds__(256) k_dwt_fused(float* __restrict__ out) {
    float* sm = (float*)smc;
    float* xs = sm + DX_OFS;
    float* lo = sm + DL_OFS;
    float* hi = sm + DH_OFS;

    int t = threadIdx.x;
    int hr0 = blockIdx.x * 16;
    int bc  = blockIdx.y;
    const float* img = g_y + (size_t)bc*HWSZ;

    // stage: input rows 2*hr0-4 .. 2*hr0+34 (39 rows), reflect
    for (int i = t; i < 9984; i += 256) {
        int r = i >> 8, w = i & 255;
        int h = refl(2*hr0 - 4 + r, HH0);
        xs[r*256 + w] = img[h*WW0 + w];
    }
    __syncthreads();

    // row filter: 16 hr x 256 w (thread t owns column w=t, loops hr)
    {
        int w = t;       // 0..255
        #pragma unroll 4
        for (int d = 0; d < 16; ++d) {
            const float* col = xs + 2*d*256 + w;
            float a0 = col[0],      a1 = col[256],  a2 = col[512],  a3 = col[768];
            float a4 = col[1024],   a5 = col[1280], a6 = col[1536], a7 = col[1792];
            float a8 = col[2048];
            float lv = c_H0[0]*a0 + c_H0[1]*a1 + c_H0[2]*a2 + c_H0[3]*a3 + c_H0[4]*a4
                     + c_H0[5]*a5 + c_H0[6]*a6 + c_H0[7]*a7 + c_H0[8]*a8;
            float hv = c_H1[0]*a1 + c_H1[1]*a2 + c_H1[2]*a3 + c_H1[3]*a4
                     + c_H1[4]*a5 + c_H1[5]*a6 + c_H1[6]*a7;
            lo[d*260 + w] = lv;
            hi[d*260 + w] = hv;
        }
    }
    __syncthreads();

    // col filter: 16 hr x 128 wr, 4 bands, write to out
    size_t obase = (size_t)bc*HD*WD;
    for (int i = t; i < 2048; i += 256) {
        int wr = i & 127, d = i >> 7;
        const float* lrow = lo + d*260;
        const float* hrow = hi + d*260;
        float rl[9], rh[9];
        #pragma unroll
        for (int k = 0; k < 9; ++k) {
            int j = refl(2*wr + k - 4, WW0);
            rl[k] = lrow[j];
            rh[k] = hrow[j];
        }
        float ll = 0.f, lh = 0.f, hl = 0.f, hh = 0.f;
        #pragma unroll
        for (int k = 0; k < 9; ++k) { ll += c_H0[k]*rl[k]; hl += c_H0[k]*rh[k]; }
        #pragma unroll
        for (int k = 0; k < 7; ++k) { lh += c_H1[k]*rl[k+1]; hh += c_H1[k]*rh[k+1]; }
        size_t oidx = obase + (size_t)(hr0 + d)*WD + wr;
        out[OFS_LL + oidx] = ll;
        out[OFS_LH + oidx] = lh;
        out[OFS_HL + oidx] = hl;
        out[OFS_HH + oidx] = hh;
    }
}

// ---------------- K6: mask downsample along H ----------------
__global__ void k_mask_rows() {
    int idx = blockIdx.x*256 + threadIdx.x;
    int wx = idx & 255;
    int hr = (idx >> 8) & 127;
    int b  = idx >> 15;
    const float* mb = g_mvalid + (size_t)b*HWSZ + wx;
    float s9 = 0.f, s7 = 0.f;
    #pragma unroll
    for (int k = 0; k < 9; ++k) {
        float v = mb[refl(2*hr + k - 4, HH0) * WW0];
        s9 += v;
        if (k >= 1 && k <= 7) s7 += v;
    }
    g_mlo[idx] = (s9 > 0.f) ? 1.f : 0.f;
    g_mhi[idx] = (s7 > 0.f) ? 1.f : 0.f;
}

// ---------------- K7: mask downsample along W -> out ----------------
__global__ void k_mask_cols(float* __restrict__ out) {
    int idx = blockIdx.x*256 + threadIdx.x;
    int wr = idx & 127;
    int hr = (idx >> 7) & 127;
    int b  = idx >> 14;
    const float* lrow = g_mlo + ((size_t)b*HD + hr)*WW0;
    const float* hrow = g_mhi + ((size_t)b*HD + hr)*WW0;
    float s9l = 0.f, s7l = 0.f, s9h = 0.f, s7h = 0.f;
    #pragma unroll
    for (int k = 0; k < 9; ++k) {
        int j = refl(2*wr + k - 4, WW0);
        float vl = lrow[j], vh = hrow[j];
        s9l += vl; s9h += vh;
        if (k >= 1 && k <= 7) { s7l += vl; s7h += vh; }
    }
    out[OFS_MLL + idx] = (s9l > 0.f) ? 1.f : 0.f;
    out[OFS_MLH + idx] = (s7l > 0.f) ? 1.f : 0.f;
    out[OFS_MHL + idx] = (s9h > 0.f) ? 1.f : 0.f;
    out[OFS_MHH + idx] = (s7h > 0.f) ? 1.f : 0.f;
}

// ---------------- launch ----------------
extern "C" void kernel_launch(void* const* d_in, const int* in_sizes, int n_in,
                              void* d_out, int out_size) {
    const float* tensor = (const float*)d_in[0];
    const float* mask   = (const float*)d_in[1];
    const float* weight = (const float*)d_in[2];
    const float* bias   = (const float*)d_in[3];
    const float* u      = (const float*)d_in[4];
    const float* beta   = (const float*)d_in[5];
    const float* gamma  = (const float*)d_in[6];
    float* out = (float*)d_out;

    cudaFuncSetAttribute(k_conv_mma, cudaFuncAttributeMaxDynamicSharedMemorySize, SMEM_MMA);
    cudaFuncSetAttribute(k_dwt_fused, cudaFuncAttributeMaxDynamicSharedMemorySize, SMEM_DWT);

    k_sigma<<<1, 576>>>(weight, u);
    k_prepw<<<288, 256>>>();
    k_ratio<<<(NB*HWSZ)/256, 256>>>(mask);
    k_conv_mma<<<dim3(4, 128, NB), 256, SMEM_MMA>>>(tensor, mask, bias);
    k_gdn<<<(NB*HWSZ)/128, 256>>>(gamma, beta);
    k_dwt_fused<<<dim3(8, NB*CO), 256, SMEM_DWT>>>(out);
    k_mask_rows<<<(NB*HD*WW0)/256, 256>>>();
    k_mask_cols<<<(NB*HD*WD)/256, 256>>>(out);
}

// round 11
// speedup vs baseline: 1.5333x; 1.2808x over previous
#include <cuda_runtime.h>
#include <cuda_bf16.h>
#include <math.h>
#include <stdint.h>

#define NB   8
#define CIN  64
#define CO   128
#define HH0  256
#define WW0  256
#define HWSZ 65536
#define HD   128
#define WD   128

// ---------------- scratch ----------------
__device__ float g_wsn[CO*CIN*9];
__device__ unsigned char g_wB[9*34816];     // per-tap [hi|lo][64 c-rows x 272B (128 o bf16 + pad)]
__device__ float g_ratio[NB*HWSZ];
__device__ float g_mvalid[NB*HWSZ];
__device__ float g_y[(size_t)NB*CO*HWSZ];
__device__ float g_mlo[NB*HD*WW0];
__device__ float g_mhi[NB*HD*WW0];

__constant__ float c_H0[9] = {
    0.026748757410810f, -0.016864118442875f, -0.078223266528990f,
    0.266864118442875f,  0.602949018236360f,  0.266864118442875f,
   -0.078223266528990f, -0.016864118442875f,  0.026748757410810f};
__constant__ float c_H1[7] = {
    0.091271763114250f, -0.057543526228500f, -0.591271763114250f,
    1.115087052457000f, -0.591271763114250f, -0.057543526228500f,
    0.091271763114250f};

#define SZ_BAND ((size_t)NB*CO*HD*WD)
#define SZ_MASK ((size_t)NB*HD*WD)
#define OFS_LL   ((size_t)0)
#define OFS_MLL  (OFS_LL  + SZ_BAND)
#define OFS_LH   (OFS_MLL + SZ_MASK)
#define OFS_HL   (OFS_LH  + SZ_BAND)
#define OFS_HH   (OFS_HL  + SZ_BAND)
#define OFS_MLH  (OFS_HH  + SZ_BAND)
#define OFS_MHL  (OFS_MLH + SZ_MASK)
#define OFS_MHH  (OFS_MHL + SZ_MASK)

__device__ __forceinline__ int refl(int j, int n) {
    if (j < 0) j = -j;
    if (j >= n) j = 2*n - 2 - j;
    return j;
}

// ---------------- mma.sync / ldmatrix / cp.async helpers (baseline PTX, sm_80+) ----------
__device__ __forceinline__ uint32_t smem_u32(const void* p) {
    uint32_t a;
    asm("{ .reg .u64 t; cvta.to.shared.u64 t, %1; cvt.u32.u64 %0, t; }" : "=r"(a) : "l"(p));
    return a;
}
__device__ __forceinline__ void ldsm4(uint32_t* r, uint32_t a) {
    asm volatile("ldmatrix.sync.aligned.m8n8.x4.shared.b16 {%0,%1,%2,%3}, [%4];"
        : "=r"(r[0]), "=r"(r[1]), "=r"(r[2]), "=r"(r[3]) : "r"(a));
}
__device__ __forceinline__ void ldsm4t(uint32_t* r, uint32_t a) {
    asm volatile("ldmatrix.sync.aligned.m8n8.x4.trans.shared.b16 {%0,%1,%2,%3}, [%4];"
        : "=r"(r[0]), "=r"(r[1]), "=r"(r[2]), "=r"(r[3]) : "r"(a));
}
__device__ __forceinline__ void mma16816(float* c, const uint32_t* a, const uint32_t* b) {
    asm volatile("mma.sync.aligned.m16n8k16.row.col.f32.bf16.bf16.f32 "
        "{%0,%1,%2,%3},{%4,%5,%6,%7},{%8,%9},{%0,%1,%2,%3};"
        : "+f"(c[0]), "+f"(c[1]), "+f"(c[2]), "+f"(c[3])
        : "r"(a[0]), "r"(a[1]), "r"(a[2]), "r"(a[3]), "r"(b[0]), "r"(b[1]));
}
__device__ __forceinline__ void cpa16(uint32_t s, const void* g) {
    asm volatile("cp.async.cg.shared.global [%0], [%1], 16;" :: "r"(s), "l"(g) : "memory");
}
__device__ __forceinline__ void cpa_commit() {
    asm volatile("cp.async.commit_group;" ::: "memory");
}
__device__ __forceinline__ void cpa_wait0() {
    asm volatile("cp.async.wait_group 0;" ::: "memory");
}

// ---------------- K0: spectral norm -> g_wsn ----------------
__global__ void k_sigma(const float* __restrict__ w, const float* __restrict__ u) {
    __shared__ float sv[576];
    __shared__ float red[576];
    __shared__ float s_bcast;
    int t = threadIdx.x;

    float vj = 0.f;
    for (int o = 0; o < CO; ++o) vj += w[o*576 + t] * u[o];
    red[t] = vj*vj;
    sv[t] = vj;
    __syncthreads();
    if (t == 0) {
        float s = 0.f;
        for (int i = 0; i < 576; ++i) s += red[i];
        s_bcast = 1.f / (sqrtf(s) + 1e-12f);
    }
    __syncthreads();
    float vn = sv[t] * s_bcast;
    __syncthreads();
    sv[t] = vn;
    __syncthreads();

    if (t < CO) {
        float s = 0.f;
        for (int j = 0; j < 576; ++j) s += w[t*576 + j] * sv[j];
        red[t] = s*s;
    }
    __syncthreads();
    if (t == 0) {
        float s = 0.f;
        for (int i = 0; i < CO; ++i) s += red[i];
        s_bcast = 1.f / sqrtf(s);
    }
    __syncthreads();
    float inv_sigma = s_bcast;
    for (int i = t; i < CO*CIN*9; i += 576) g_wsn[i] = w[i] * inv_sigma;
}

// ---------------- K0b: weights -> per-tap [c][o] bf16 hi/lo rows (272B stride) --------
__global__ void k_prepw() {
    int idx = blockIdx.x*256 + threadIdx.x;
    if (idx >= 9*CIN*CO) return;
    int q = idx >> 13;
    int rem = idx & 8191;
    int c = rem >> 7;
    int o = rem & 127;
    float v = g_wsn[(o*CIN + c)*9 + q];
    __nv_bfloat16 hi = __float2bfloat16(v);
    __nv_bfloat16 lo = __float2bfloat16(v - __bfloat162float(hi));
    size_t base = (size_t)q*34816;
    *(__nv_bfloat16*)(g_wB + base +         c*272 + o*2) = hi;
    *(__nv_bfloat16*)(g_wB + base + 17408 + c*272 + o*2) = lo;
}

// ---------------- K1: mask 3x3 box -> ratio + valid ----------------
__global__ void k_ratio(const float* __restrict__ mask) {
    int idx = blockIdx.x*256 + threadIdx.x;
    int b = idx >> 16;
    int hw = idx & 65535;
    int h = hw >> 8, wx = hw & 255;
    const float* mb = mask + (size_t)b*HWSZ;
    float s = 0.f;
    #pragma unroll
    for (int dh = -1; dh <= 1; ++dh) {
        int h2 = h + dh;
        if (h2 < 0 || h2 >= HH0) continue;
        #pragma unroll
        for (int dw = -1; dw <= 1; ++dw) {
            int w2 = wx + dw;
            if (w2 < 0 || w2 >= WW0) continue;
            s += mb[h2*WW0 + w2];
        }
    }
    bool valid = s > 0.f;
    g_mvalid[idx] = valid ? 1.f : 0.f;
    g_ratio[idx]  = valid ? 9.f / fmaxf(s, 1e-8f) : 0.f;
}

// ---------------- K2: mma.sync implicit-GEMM conv (bf16 3-term split) ----------------
// Single-buffered weights (34816B) -> smem 110848 -> 2 CTAs/SM; tap-load stall
// is hidden by the co-resident CTA.
#define P_HI 0
#define P_LO 38016
#define BW0  76032
#define SMEM_MMA 110848

extern __shared__ char smc[];

__global__ void __launch_bounds__(256, 2) k_conv_mma(const float* __restrict__ x,
                                                     const float* __restrict__ mask,
                                                     const float* __restrict__ bias) {
    uint32_t sb = smem_u32(smc);
    int t = threadIdx.x, l = t & 31, wid = t >> 5;
    int w0 = blockIdx.x * 64, h0 = blockIdx.y * 2, b = blockIdx.z;
    int warp_m = wid & 1;
    int warp_n = wid >> 1;

    // prefetch tap 0
    for (int i = t; i < 2176; i += 256)
        cpa16(sb + BW0 + i*16, g_wB + i*16);
    cpa_commit();

    // patch fill: 64c x 4rows x 66w of (x*mask), bf16 hi/lo
    for (int i = t; i < 16896; i += 256) {
        int w = i % 66;
        int rem = i / 66;
        int r = rem & 3;
        int c = rem >> 2;
        int h = h0 - 1 + r, wx = w0 - 1 + w;
        float v = 0.f;
        if (h >= 0 && h < HH0 && wx >= 0 && wx < WW0)
            v = x[(((size_t)b*CIN + c)*HH0 + h)*WW0 + wx]
              * mask[((size_t)b*HH0 + h)*WW0 + wx];
        __nv_bfloat16 hi = __float2bfloat16(v);
        __nv_bfloat16 lo = __float2bfloat16(v - __bfloat162float(hi));
        int off = (r*66 + w)*144 + c*2;
        *(__nv_bfloat16*)(smc + P_HI + off) = hi;
        *(__nv_bfloat16*)(smc + P_LO + off) = lo;
    }
    cpa_wait0();
    __syncthreads();

    float acc[4][4][4];
    #pragma unroll
    for (int mi = 0; mi < 4; ++mi)
        #pragma unroll
        for (int ni = 0; ni < 4; ++ni)
            #pragma unroll
            for (int k = 0; k < 4; ++k) acc[mi][ni][k] = 0.f;

    int lane15 = l & 15;
    int kh8 = ((l >> 4) & 1) * 8;
    int noff = ((l >> 4) & 1) * 8;

    for (int q = 0; q < 9; ++q) {
        int kh = q / 3, kw = q - kh*3;
        uint32_t bwbase = sb + BW0;
        int prow0 = ((warp_m + kh)*66 + kw) * 144;

        #pragma unroll
        for (int ks = 0; ks < 4; ++ks) {
            int k0 = ks * 16;
            uint32_t aH[4][4], aL[4][4];
            #pragma unroll
            for (int mi = 0; mi < 4; ++mi) {
                uint32_t off = (uint32_t)(prow0 + (mi*16 + lane15)*144 + (k0 + kh8)*2);
                ldsm4(aH[mi], sb + P_HI + off);
                ldsm4(aL[mi], sb + P_LO + off);
            }
            uint32_t bH[2][4], bL[2][4];
            #pragma unroll
            for (int n2 = 0; n2 < 2; ++n2) {
                uint32_t boff = (uint32_t)((k0 + lane15)*272 + (warp_n*32 + n2*16 + noff)*2);
                ldsm4t(bH[n2], bwbase + boff);
                ldsm4t(bL[n2], bwbase + 17408 + boff);
            }
            #pragma unroll
            for (int mi = 0; mi < 4; ++mi)
                #pragma unroll
                for (int ni = 0; ni < 4; ++ni) {
                    const uint32_t* bh = &bH[ni >> 1][(ni & 1)*2];
                    const uint32_t* bl = &bL[ni >> 1][(ni & 1)*2];
                    mma16816(acc[mi][ni], aH[mi], bh);
                    mma16816(acc[mi][ni], aH[mi], bl);
                    mma16816(acc[mi][ni], aL[mi], bh);
                }
        }

        __syncthreads();    // all warps done reading BW0 before overwrite
        if (q < 8) {
            const unsigned char* src = g_wB + (size_t)(q + 1)*34816;
            for (int i = t; i < 2176; i += 256)
                cpa16(sb + BW0 + i*16, src + i*16);
            cpa_commit();
            cpa_wait0();
            __syncthreads();
        }
    }

    __syncthreads();
    float* D = (float*)smc;
    #pragma unroll
    for (int mi = 0; mi < 4; ++mi)
        #pragma unroll
        for (int ni = 0; ni < 4; ++ni) {
            int px = warp_m*64 + mi*16 + (l >> 2);
            int o  = warp_n*32 + ni*8 + 2*(l & 3);
            D[o*130 + px]           = acc[mi][ni][0];
            D[(o + 1)*130 + px]     = acc[mi][ni][1];
            D[o*130 + px + 8]       = acc[mi][ni][2];
            D[(o + 1)*130 + px + 8] = acc[mi][ni][3];
        }
    __syncthreads();

    int wp = t & 63, og = t >> 6;
    #pragma unroll
    for (int r = 0; r < 2; ++r) {
        int h = h0 + r;
        int wg = w0 + wp;
        float rt = g_ratio[((size_t)b*HH0 + h)*WW0 + wg];
        #pragma unroll 8
        for (int oo = 0; oo < 32; ++oo) {
            int o = oo*4 + og;
            float v = D[o*130 + r*64 + wp];
            g_y[(((size_t)b*CO + o)*HH0 + h)*WW0 + wg] = (rt > 0.f) ? v*rt + bias[o] : 0.f;
        }
    }
}

// ---------------- K3: GDN (in-place), scalar GEMM with vectorized smem/gmem ----------
// thread (px,oy): outputs o = oy*8+i, pixels p = px*8+j (8 consecutive -> float4 IO)
__global__ void __launch_bounds__(256) k_gdn(const float* __restrict__ gamma,
                                             const float* __restrict__ beta) {
    __shared__ float zs[16][128];
    __shared__ float gsT[16][132];   // [k][o], row pad 132 (16B aligned)

    size_t p0 = (size_t)blockIdx.x * 128;
    int b   = (int)(p0 >> 16);
    int hw0 = (int)(p0 & 65535);
    int t = threadIdx.x;
    int px = t & 15, oy = t >> 4;

    float acc[8][8];
    #pragma unroll
    for (int i = 0; i < 8; ++i)
        #pragma unroll
        for (int j = 0; j < 8; ++j) acc[i][j] = 0.f;

    float* yb = g_y + (size_t)b*CO*HWSZ + hw0;

    for (int c0 = 0; c0 < CO; c0 += 16) {
        __syncthreads();
        for (int i = t; i < 2048; i += 256) {        // z = x^2 chunk [16][128]
            int k = i >> 7, p = i & 127;
            float v = yb[(size_t)(c0 + k)*HWSZ + p];
            zs[k][p] = v*v;
        }
        for (int i = t; i < 2048; i += 256) {        // gamma chunk transposed [k][o]
            int o = i >> 4, k = i & 15;
            gsT[k][o] = gamma[o*CO + c0 + k];
        }
        __syncthreads();
        #pragma unroll
        for (int k = 0; k < 16; ++k) {
            float4 a0 = *(const float4*)&gsT[k][oy*8];
            float4 a1 = *(const float4*)&gsT[k][oy*8 + 4];
            float4 b0 = *(const float4*)&zs[k][px*8];
            float4 b1 = *(const float4*)&zs[k][px*8 + 4];
            float a[8] = {a0.x, a0.y, a0.z, a0.w, a1.x, a1.y, a1.z, a1.w};
            float bb[8] = {b0.x, b0.y, b0.z, b0.w, b1.x, b1.y, b1.z, b1.w};
            #pragma unroll
            for (int i = 0; i < 8; ++i)
                #pragma unroll
                for (int j = 0; j < 8; ++j) acc[i][j] += a[i]*bb[j];
        }
    }

    float4 m0 = *(const float4*)&g_mvalid[p0 + px*8];
    float4 m1 = *(const float4*)&g_mvalid[p0 + px*8 + 4];
    float mv[8] = {m0.x, m0.y, m0.z, m0.w, m1.x, m1.y, m1.z, m1.w};
    #pragma unroll
    for (int i = 0; i < 8; ++i) {
        int o = oy*8 + i;
        float bo = beta[o];
        size_t ad = (size_t)o*HWSZ + px*8;
        float4 x0 = *(const float4*)&yb[ad];
        float4 x1 = *(const float4*)&yb[ad + 4];
        float xv[8] = {x0.x, x0.y, x0.z, x0.w, x1.x, x1.y, x1.z, x1.w};
        float4 r0, r1;
        r0.x = xv[0] * rsqrtf(bo + acc[i][0]) * mv[0];
        r0.y = xv[1] * rsqrtf(bo + acc[i][1]) * mv[1];
        r0.z = xv[2] * rsqrtf(bo + acc[i][2]) * mv[2];
        r0.w = xv[3] * rsqrtf(bo + acc[i][3]) * mv[3];
        r1.x = xv[4] * rsqrtf(bo + acc[i][4]) * mv[4];
        r1.y = xv[5] * rsqrtf(bo + acc[i][5]) * mv[5];
        r1.z = xv[6] * rsqrtf(bo + acc[i][6]) * mv[6];
        r1.w = xv[7] * rsqrtf(bo + acc[i][7]) * mv[7];
        *(float4*)&yb[ad]     = r0;
        *(float4*)&yb[ad + 4] = r1;
    }
}

// ---------------- K4: fused DWT (rows + cols in one pass) -> 4 bands ----------------
#define DX_OFS 0          // xs[39][256] floats
#define DL_OFS 9984       // lo[16][260]
#define DH_OFS 14144      // hi[16][260]
#define SMEM_DWT 73216    // 18304 floats

__global__ void __launch_bounds__(256) k_dwt_fused(float* __restrict__ out) {
    float* sm = (float*)smc;
    float* xs = sm + DX_OFS;
    float* lo = sm + DL_OFS;
    float* hi = sm + DH_OFS;

    int t = threadIdx.x;
    int hr0 = blockIdx.x * 16;
    int bc  = blockIdx.y;
    const float* img = g_y + (size_t)bc*HWSZ;

    for (int i = t; i < 9984; i += 256) {
        int r = i >> 8, w = i & 255;
        int h = refl(2*hr0 - 4 + r, HH0);
        xs[r*256 + w] = img[h*WW0 + w];
    }
    __syncthreads();

    {
        int w = t;
        #pragma unroll 4
        for (int d = 0; d < 16; ++d) {
            const float* col = xs + 2*d*256 + w;
            float a0 = col[0],      a1 = col[256],  a2 = col[512],  a3 = col[768];
            float a4 = col[1024],   a5 = col[1280], a6 = col[1536], a7 = col[1792];
            float a8 = col[2048];
            float lv = c_H0[0]*a0 + c_H0[1]*a1 + c_H0[2]*a2 + c_H0[3]*a3 + c_H0[4]*a4
                     + c_H0[5]*a5 + c_H0[6]*a6 + c_H0[7]*a7 + c_H0[8]*a8;
            float hv = c_H1[0]*a1 + c_H1[1]*a2 + c_H1[2]*a3 + c_H1[3]*a4
                     + c_H1[4]*a5 + c_H1[5]*a6 + c_H1[6]*a7;
            lo[d*260 + w] = lv;
            hi[d*260 + w] = hv;
        }
    }
    __syncthreads();

    size_t obase = (size_t)bc*HD*WD;
    for (int i = t; i < 2048; i += 256) {
        int wr = i & 127, d = i >> 7;
        const float* lrow = lo + d*260;
        const float* hrow = hi + d*260;
        float rl[9], rh[9];
        #pragma unroll
        for (int k = 0; k < 9; ++k) {
            int j = refl(2*wr + k - 4, WW0);
            rl[k] = lrow[j];
            rh[k] = hrow[j];
        }
        float ll = 0.f, lh = 0.f, hl = 0.f, hh = 0.f;
        #pragma unroll
        for (int k = 0; k < 9; ++k) { ll += c_H0[k]*rl[k]; hl += c_H0[k]*rh[k]; }
        #pragma unroll
        for (int k = 0; k < 7; ++k) { lh += c_H1[k]*rl[k+1]; hh += c_H1[k]*rh[k+1]; }
        size_t oidx = obase + (size_t)(hr0 + d)*WD + wr;
        out[OFS_LL + oidx] = ll;
        out[OFS_LH + oidx] = lh;
        out[OFS_HL + oidx] = hl;
        out[OFS_HH + oidx] = hh;
    }
}

// ---------------- K6: mask downsample along H ----------------
__global__ void k_mask_rows() {
    int idx = blockIdx.x*256 + threadIdx.x;
    int wx = idx & 255;
    int hr = (idx >> 8) & 127;
    int b  = idx >> 15;
    const float* mb = g_mvalid + (size_t)b*HWSZ + wx;
    float s9 = 0.f, s7 = 0.f;
    #pragma unroll
    for (int k = 0; k < 9; ++k) {
        float v = mb[refl(2*hr + k - 4, HH0) * WW0];
        s9 += v;
        if (k >= 1 && k <= 7) s7 += v;
    }
    g_mlo[idx] = (s9 > 0.f) ? 1.f : 0.f;
    g_mhi[idx] = (s7 > 0.f) ? 1.f : 0.f;
}

// ---------------- K7: mask downsample along W -> out ----------------
__global__ void k_mask_cols(float* __restrict__ out) {
    int idx = blockIdx.x*256 + threadIdx.x;
    int wr = idx & 127;
    int hr = (idx >> 7) & 127;
    int b  = idx >> 14;
    const float* lrow = g_mlo + ((size_t)b*HD + hr)*WW0;
    const float* hrow = g_mhi + ((size_t)b*HD + hr)*WW0;
    float s9l = 0.f, s7l = 0.f, s9h = 0.f, s7h = 0.f;
    #pragma unroll
    for (int k = 0; k < 9; ++k) {
        int j = refl(2*wr + k - 4, WW0);
        float vl = lrow[j], vh = hrow[j];
        s9l += vl; s9h += vh;
        if (k >= 1 && k <= 7) { s7l += vl; s7h += vh; }
    }
    out[OFS_MLL + idx] = (s9l > 0.f) ? 1.f : 0.f;
    out[OFS_MLH + idx] = (s7l > 0.f) ? 1.f : 0.f;
    out[OFS_MHL + idx] = (s9h > 0.f) ? 1.f : 0.f;
    out[OFS_MHH + idx] = (s7h > 0.f) ? 1.f : 0.f;
}

// ---------------- launch ----------------
extern "C" void kernel_launch(void* const* d_in, const int* in_sizes, int n_in,
                              void* d_out, int out_size) {
    const float* tensor = (const float*)d_in[0];
    const float* mask   = (const float*)d_in[1];
    const float* weight = (const float*)d_in[2];
    const float* bias   = (const float*)d_in[3];
    const float* u      = (const float*)d_in[4];
    const float* beta   = (const float*)d_in[5];
    const float* gamma  = (const float*)d_in[6];
    float* out = (float*)d_out;

    cudaFuncSetAttribute(k_conv_mma, cudaFuncAttributeMaxDynamicSharedMemorySize, SMEM_MMA);
    cudaFuncSetAttribute(k_dwt_fused, cudaFuncAttributeMaxDynamicSharedMemorySize, SMEM_DWT);

    k_sigma<<<1, 576>>>(weight, u);
    k_prepw<<<288, 256>>>();
    k_ratio<<<(NB*HWSZ)/256, 256>>>(mask);
    k_conv_mma<<<dim3(4, 128, NB), 256, SMEM_MMA>>>(tensor, mask, bias);
    k_gdn<<<(NB*HWSZ)/128, 256>>>(gamma, beta);
    k_dwt_fused<<<dim3(8, NB*CO), 256, SMEM_DWT>>>(out);
    k_mask_rows<<<(NB*HD*WW0)/256, 256>>>();
    k_mask_cols<<<(NB*HD*WD)/256, 256>>>(out);
}